// round 8
// baseline (speedup 1.0000x reference)
#include <cuda_runtime.h>
#include <cuda_bf16.h>
#include <math.h>
#include <stdint.h>

#define N_NODES 20000
#define E_EDGES 320000
#define F_IN    1024
#define H_MID   256
#define D_OUT   128
#define QKVS    512
#define STAT_BLOCKS 512
#define M_TILES ((N_NODES + 127) / 128)

// ---------------- scratch (static device globals; no allocations) ----------------
__device__ __align__(16) float  g_g[(size_t)N_NODES * H_MID];
__device__ __align__(16) float  g_qkvs[(size_t)N_NODES * QKVS];
__device__ __align__(16) float  g_alpha[E_EDGES];
__device__ float  g_dinv[N_NODES];
__device__ int    g_degcnt[N_NODES];
__device__ int    g_fill[N_NODES];
__device__ int    g_rowptr[N_NODES + 1];
__device__ int    g_csrc[E_EDGES];
__device__ int    g_ceid[E_EDGES];
__device__ double g_part[STAT_BLOCKS][2];
__device__ float  g_stats[2];
__device__ __align__(16) float  g_bcat[QKVS];
// bf16 split operands
__device__ __align__(16) __nv_bfloat16 g_B1hi[(size_t)H_MID * F_IN];   // W_gcn^T [256][1024]
__device__ __align__(16) __nv_bfloat16 g_B1lo[(size_t)H_MID * F_IN];
__device__ __align__(16) __nv_bfloat16 g_Hhi[(size_t)N_NODES * H_MID]; // split h (from k_agg)
__device__ __align__(16) __nv_bfloat16 g_Hlo[(size_t)N_NODES * H_MID];
__device__ __align__(16) __nv_bfloat16 g_B2hi[(size_t)QKVS * H_MID];   // Wcat^T [512][256]
__device__ __align__(16) __nv_bfloat16 g_B2lo[(size_t)QKVS * H_MID];

// ---------------- helpers ----------------
__device__ __forceinline__ uint32_t smem_u32(const void* p) {
    uint32_t a;
    asm("{ .reg .u64 t; cvta.to.shared.u64 t, %1; cvt.u32.u64 %0, t; }" : "=r"(a) : "l"(p));
    return a;
}
__device__ __forceinline__ void mma16816(float* c, const uint32_t* a, const uint32_t* b) {
    asm volatile(
        "mma.sync.aligned.m16n8k16.row.col.f32.bf16.bf16.f32 "
        "{%0,%1,%2,%3}, {%4,%5,%6,%7}, {%8,%9}, {%0,%1,%2,%3};"
        : "+f"(c[0]), "+f"(c[1]), "+f"(c[2]), "+f"(c[3])
        : "r"(a[0]), "r"(a[1]), "r"(a[2]), "r"(a[3]), "r"(b[0]), "r"(b[1]));
}
__device__ __forceinline__ void ldm4(uint32_t* r, uint32_t addr) {
    asm volatile("ldmatrix.sync.aligned.m8n8.x4.shared.b16 {%0,%1,%2,%3}, [%4];"
        : "=r"(r[0]), "=r"(r[1]), "=r"(r[2]), "=r"(r[3]) : "r"(addr) : "memory");
}
__device__ __forceinline__ void split2(float a, float b, __nv_bfloat162& h, __nv_bfloat162& l) {
    __nv_bfloat16 ha = __float2bfloat16_rn(a);
    __nv_bfloat16 hb = __float2bfloat16_rn(b);
    h.x = ha; h.y = hb;
    l.x = __float2bfloat16_rn(a - __bfloat162float(ha));
    l.y = __float2bfloat16_rn(b - __bfloat162float(hb));
}
__device__ __forceinline__ void splitpack(float a, float b, uint32_t& hw, uint32_t& lw) {
    __nv_bfloat162 h, l;
    split2(a, b, h, l);
    hw = *(uint32_t*)&h;
    lw = *(uint32_t*)&l;
}

// ---------------- CSR build ----------------
__global__ void k_init() {
    int i = blockIdx.x * blockDim.x + threadIdx.x;
    if (i < N_NODES) { g_degcnt[i] = 0; g_fill[i] = 0; }
}

__global__ void k_hist(const int* __restrict__ ei) {
    int e = blockIdx.x * blockDim.x + threadIdx.x;
    if (e < E_EDGES) atomicAdd(&g_degcnt[ei[E_EDGES + e]], 1);
}

__global__ void k_scan() {
    const int n = N_NODES;
    const int PER = 20;
    __shared__ int wsum[32];
    int tid = threadIdx.x, lane = tid & 31, wid = tid >> 5;
    int start = tid * PER;
    int cnt[PER];
    int local = 0;
#pragma unroll
    for (int u = 0; u < PER; u++) {
        int i = start + u;
        int c = (i < n) ? g_degcnt[i] : 0;
        cnt[u] = c; local += c;
    }
    int v = local;
#pragma unroll
    for (int d = 1; d < 32; d <<= 1) { int t = __shfl_up_sync(0xffffffffu, v, d); if (lane >= d) v += t; }
    if (lane == 31) wsum[wid] = v;
    __syncthreads();
    if (wid == 0) {
        int w = wsum[lane];
#pragma unroll
        for (int d = 1; d < 32; d <<= 1) { int t = __shfl_up_sync(0xffffffffu, w, d); if (lane >= d) w += t; }
        wsum[lane] = w;
    }
    __syncthreads();
    int excl = (v - local) + (wid > 0 ? wsum[wid - 1] : 0);
    int run = excl;
#pragma unroll
    for (int u = 0; u < PER; u++) {
        int i = start + u;
        if (i < n) {
            g_rowptr[i] = run;
            g_dinv[i] = rsqrtf((float)(cnt[u] + 1));
        }
        run += cnt[u];
    }
    if (tid == 1023) g_rowptr[n] = run;
}

__global__ void k_csr(const int* __restrict__ ei) {
    int e = blockIdx.x * blockDim.x + threadIdx.x;
    if (e < E_EDGES) {
        int s = ei[e];
        int d = ei[E_EDGES + e];
        int pos = g_rowptr[d] + atomicAdd(&g_fill[d], 1);
        g_csrc[pos] = s;
        g_ceid[pos] = e;
    }
}

// ---------------- weight conversions ----------------
// W_gcn[1024,256] -> B1 [256][1024]
__global__ void k_convBW(const float* __restrict__ Wg) {
    int idx = blockIdx.x * blockDim.x + threadIdx.x;
    if (idx >= H_MID * F_IN) return;
    int n = idx >> 10, k = idx & 1023;
    float v = Wg[(size_t)k * H_MID + n];
    __nv_bfloat16 h = __float2bfloat16_rn(v);
    g_B1hi[idx] = h;
    g_B1lo[idx] = __float2bfloat16_rn(v - __bfloat162float(h));
}

// Wq|Wk|Wv|Ws [256,128] -> B2 [512][256] + bcat
__global__ void k_packB2(const float* __restrict__ Wq, const float* __restrict__ Wk,
                         const float* __restrict__ Wv, const float* __restrict__ Ws,
                         const float* __restrict__ bq, const float* __restrict__ bk,
                         const float* __restrict__ bv, const float* __restrict__ bs) {
    int idx = blockIdx.x * blockDim.x + threadIdx.x;
    if (idx >= QKVS * H_MID) return;
    int n = idx >> 8, k = idx & 255;
    int w = n >> 7, c = n & 127;
    const float* W = (w == 0) ? Wq : (w == 1) ? Wk : (w == 2) ? Wv : Ws;
    float v = W[(size_t)k * D_OUT + c];
    __nv_bfloat16 h = __float2bfloat16_rn(v);
    g_B2hi[idx] = h;
    g_B2lo[idx] = __float2bfloat16_rn(v - __bfloat162float(h));
    if (idx < QKVS) {
        int nn = idx, ww = nn >> 7, cc = nn & 127;
        const float* b = (ww == 0) ? bq : (ww == 1) ? bk : (ww == 2) ? bv : bs;
        g_bcat[nn] = b[cc];
    }
}

// ---------------- split-bf16 GEMM, double-buffered, interleaved hi|lo smem ----------------
// MODE 0: g_g = (x @ W_gcn) * dinv[row]; A = fp32 x (split in-kernel), B = g_B1, K=1024
// MODE 1: g_qkvs = h @ Wcat + bcat; A = g_Hhi/Hlo, B = g_B2, K=256
// smem row: 16 hi | 16 lo | 8 pad  (RW=40 bf16 = 80B stride, 16B-aligned, conflict-free)
#define RW 40

template <int MODE>
__global__ __launch_bounds__(256)
void k_mmagemm(const float* __restrict__ X) {
    const int K_TOT = (MODE == 0) ? F_IN : H_MID;
    const __nv_bfloat16* Bhi = (MODE == 0) ? g_B1hi : g_B2hi;
    const __nv_bfloat16* Blo = (MODE == 0) ? g_B1lo : g_B2lo;

    __shared__ __align__(16) __nv_bfloat16 sA[2][128 * RW];
    __shared__ __align__(16) __nv_bfloat16 sB[2][128 * RW];

    int tid = threadIdx.x, wid = tid >> 5, lane = tid & 31;
    int m0 = blockIdx.x * 128, n0 = blockIdx.y * 128;
    int wm = wid & 3, wn = wid >> 2;          // warp grid 4(m) x 2(n); warp tile 32x64

    int lrow = tid >> 1, lhalf = (tid & 1) << 3;
    const int NCH = K_TOT / 16;
    int arow = m0 + lrow;
    bool aok = arow < N_NODES;
    int soff = lrow * RW + lhalf;

    const float* pX = X + (size_t)arow * K_TOT + lhalf;               // MODE 0
    const __nv_bfloat16* pAh = g_Hhi + (size_t)arow * H_MID + lhalf;  // MODE 1
    const __nv_bfloat16* pAl = g_Hlo + (size_t)arow * H_MID + lhalf;
    const __nv_bfloat16* pBh = Bhi + (size_t)(n0 + lrow) * K_TOT + lhalf;
    const __nv_bfloat16* pBl = Blo + (size_t)(n0 + lrow) * K_TOT + lhalf;

    float acc[2][8][4];
#pragma unroll
    for (int a = 0; a < 2; a++)
#pragma unroll
        for (int b = 0; b < 8; b++)
#pragma unroll
            for (int c = 0; c < 4; c++) acc[a][b][c] = 0.f;

    // staging lambda: load chunk c into buffer buf
    auto stage = [&](int c, int buf) {
        uint4 vbh = *(const uint4*)(pBh + c * 16);
        uint4 vbl = *(const uint4*)(pBl + c * 16);
        *(uint4*)&sB[buf][soff] = vbh;
        *(uint4*)&sB[buf][soff + 16] = vbl;
        if (MODE == 0) {
            float4 f0 = make_float4(0.f, 0.f, 0.f, 0.f), f1 = f0;
            if (aok) {
                f0 = *(const float4*)(pX + c * 16);
                f1 = *(const float4*)(pX + c * 16 + 4);
            }
            uint4 hw, lw;
            splitpack(f0.x, f0.y, hw.x, lw.x);
            splitpack(f0.z, f0.w, hw.y, lw.y);
            splitpack(f1.x, f1.y, hw.z, lw.z);
            splitpack(f1.z, f1.w, hw.w, lw.w);
            *(uint4*)&sA[buf][soff] = hw;
            *(uint4*)&sA[buf][soff + 16] = lw;
        } else {
            uint4 z4 = make_uint4(0, 0, 0, 0);
            uint4 vah = aok ? *(const uint4*)(pAh + c * 16) : z4;
            uint4 val_ = aok ? *(const uint4*)(pAl + c * 16) : z4;
            *(uint4*)&sA[buf][soff] = vah;
            *(uint4*)&sA[buf][soff + 16] = val_;
        }
    };

    int g8 = lane >> 3, w8 = lane & 7;
    // A x4 groups: (m0-7,k0-7),(m8-15,k0-7),(m0-7,k8-15),(m8-15,k8-15)
    uint32_t a_off = (uint32_t)((((((g8 & 1) << 3) + w8) + wm * 32) * RW + ((g8 >> 1) << 3)) * 2);
    // B x4 groups: (n0-7,k0-7),(n0-7,k8-15),(n8-15,k0-7),(n8-15,k8-15)
    uint32_t b_off = (uint32_t)((((((g8 >> 1) << 3) + w8) + wn * 64) * RW + ((g8 & 1) << 3)) * 2);

    stage(0, 0);
    __syncthreads();

    for (int c = 0; c < NCH; c++) {
        int buf = c & 1;
        if (c + 1 < NCH) stage(c + 1, buf ^ 1);   // writes peer buffer: safe (drained 1 sync ago)

        uint32_t baseA = smem_u32(sA[buf]);
        uint32_t baseB = smem_u32(sB[buf]);
        uint32_t ah[2][4], al[2][4], bh[4][4], bl[4][4];
#pragma unroll
        for (int mb = 0; mb < 2; mb++) {
            ldm4(ah[mb], baseA + a_off + mb * 16 * RW * 2);
            ldm4(al[mb], baseA + a_off + mb * 16 * RW * 2 + 32);   // lo at +16 elems
        }
#pragma unroll
        for (int q = 0; q < 4; q++) {
            ldm4(bh[q], baseB + b_off + q * 16 * RW * 2);
            ldm4(bl[q], baseB + b_off + q * 16 * RW * 2 + 32);
        }
#pragma unroll
        for (int mb = 0; mb < 2; mb++)
#pragma unroll
            for (int q = 0; q < 4; q++)
#pragma unroll
                for (int hh = 0; hh < 2; hh++) {
                    float* ca = acc[mb][q * 2 + hh];
                    mma16816(ca, ah[mb], &bh[q][hh * 2]);
                    mma16816(ca, al[mb], &bh[q][hh * 2]);
                    mma16816(ca, ah[mb], &bl[q][hh * 2]);
                }
        __syncthreads();
    }

    const int CS = (MODE == 0) ? H_MID : QKVS;
    float* Cp = (MODE == 0) ? g_g : g_qkvs;
#pragma unroll
    for (int mb = 0; mb < 2; mb++) {
        int rbase = m0 + wm * 32 + mb * 16 + (lane >> 2);
#pragma unroll
        for (int hf = 0; hf < 2; hf++) {
            int r = rbase + hf * 8;
            if (r >= N_NODES) continue;
            float rs = (MODE == 0) ? g_dinv[r] : 1.f;
#pragma unroll
            for (int n8 = 0; n8 < 8; n8++) {
                int col = n0 + wn * 64 + n8 * 8 + ((lane & 3) << 1);
                float v0 = acc[mb][n8][hf * 2 + 0];
                float v1 = acc[mb][n8][hf * 2 + 1];
                if (MODE == 0) { v0 *= rs; v1 *= rs; }
                else { v0 += g_bcat[col]; v1 += g_bcat[col + 1]; }
                float2 o; o.x = v0; o.y = v1;
                *(float2*)(Cp + (size_t)r * CS + col) = o;
            }
        }
    }
}

// ---------------- GCN aggregation: writes bf16 hi/lo split of h directly ----------------
__global__ __launch_bounds__(H_MID)
void k_agg(const float* __restrict__ b_gcn) {
    int i = blockIdx.x;
    int f = threadIdx.x;
    float acc = g_g[(size_t)i * H_MID + f];
    __shared__ int sj[H_MID];
    int s0 = g_rowptr[i], e0 = g_rowptr[i + 1];
    for (int base = s0; base < e0; base += H_MID) {
        int cnt = min(H_MID, e0 - base);
        if (f < cnt) sj[f] = g_csrc[base + f];
        __syncthreads();
        for (int p = 0; p < cnt; p++)
            acc += g_g[(size_t)sj[p] * H_MID + f];
        __syncthreads();
    }
    float v = g_dinv[i] * acc + b_gcn[f];
    v = (v >= 0.f) ? v : 0.01f * v;
    __nv_bfloat16 h = __float2bfloat16_rn(v);
    g_Hhi[(size_t)i * H_MID + f] = h;
    g_Hlo[(size_t)i * H_MID + f] = __float2bfloat16_rn(v - __bfloat162float(h));
}

// ---------------- fused attention logits + partial stats ----------------
__global__ __launch_bounds__(256)
void k_alpha_stats(const int* __restrict__ ei) {
    int wid = threadIdx.x >> 5, lane = threadIdx.x & 31;
    double s = 0.0, s2 = 0.0;
    for (int e = blockIdx.x * 8 + wid; e < E_EDGES; e += STAT_BLOCKS * 8) {
        int sn = ei[e], d = ei[E_EDGES + e];
        const float4* q = (const float4*)(g_qkvs + (size_t)d * QKVS);
        const float4* k = (const float4*)(g_qkvs + (size_t)sn * QKVS + D_OUT);
        float4 a = q[lane], b = k[lane];
        float p = a.x * b.x + a.y * b.y + a.z * b.z + a.w * b.w;
#pragma unroll
        for (int o = 16; o; o >>= 1) p += __shfl_xor_sync(0xffffffffu, p, o);
        if (lane == 0) {
            float v = p * 0.08838834764831845f;   // 1/sqrt(128)
            g_alpha[e] = v;
            s += (double)v;
            s2 += (double)v * (double)v;
        }
    }
#pragma unroll
    for (int o = 16; o; o >>= 1) {
        s  += __shfl_down_sync(0xffffffffu, s,  o);
        s2 += __shfl_down_sync(0xffffffffu, s2, o);
    }
    __shared__ double ws[8], ws2[8];
    if (lane == 0) { ws[wid] = s; ws2[wid] = s2; }
    __syncthreads();
    if (threadIdx.x == 0) {
        double ts = 0.0, ts2 = 0.0;
        for (int w = 0; w < 8; w++) { ts += ws[w]; ts2 += ws2[w]; }
        g_part[blockIdx.x][0] = ts;
        g_part[blockIdx.x][1] = ts2;
    }
}

__global__ __launch_bounds__(STAT_BLOCKS)
void k_finalize() {
    int t = threadIdx.x;
    double s = g_part[t][0], s2 = g_part[t][1];
#pragma unroll
    for (int o = 16; o; o >>= 1) {
        s  += __shfl_down_sync(0xffffffffu, s,  o);
        s2 += __shfl_down_sync(0xffffffffu, s2, o);
    }
    __shared__ double ws[16], ws2[16];
    int lane = t & 31, wid = t >> 5;
    if (lane == 0) { ws[wid] = s; ws2[wid] = s2; }
    __syncthreads();
    if (t == 0) {
        double ts = 0.0, ts2 = 0.0;
        for (int w = 0; w < STAT_BLOCKS / 32; w++) { ts += ws[w]; ts2 += ws2[w]; }
        double En = (double)E_EDGES;
        double mean = ts / En;
        double var = (ts2 - En * mean * mean) / (En - 1.0);   // ddof=1
        g_stats[0] = (float)mean;
        g_stats[1] = (float)(3.0 / sqrt(var));                // SCALE_PARAM/std
    }
}

// ---------------- output: out[i] = s[i] + sum sigmoid(alpha)*v[src] ----------------
__global__ __launch_bounds__(D_OUT)
void k_out(float* __restrict__ out) {
    int i = blockIdx.x;
    int f = threadIdx.x;
    float mean = g_stats[0], sc = g_stats[1];
    float acc = g_qkvs[(size_t)i * QKVS + 384 + f];
    __shared__ int   sj[D_OUT];
    __shared__ float sa[D_OUT];
    int s0 = g_rowptr[i], e0 = g_rowptr[i + 1];
    for (int base = s0; base < e0; base += D_OUT) {
        int cnt = min(D_OUT, e0 - base);
        if (f < cnt) {
            sj[f] = g_csrc[base + f];
            float a = (g_alpha[g_ceid[base + f]] - mean) * sc;
            sa[f] = 1.0f / (1.0f + expf(-a));
        }
        __syncthreads();
        for (int p = 0; p < cnt; p++)
            acc += g_qkvs[(size_t)sj[p] * QKVS + 256 + f] * sa[p];
        __syncthreads();
    }
    out[(size_t)i * D_OUT + f] = acc;
}

// ---------------- launch ----------------
extern "C" void kernel_launch(void* const* d_in, const int* in_sizes, int n_in,
                              void* d_out, int out_size) {
    (void)in_sizes; (void)n_in; (void)out_size;
    const float* x     = (const float*)d_in[0];
    const int*   ei    = (const int*)d_in[1];
    const float* W_gcn = (const float*)d_in[2];
    const float* b_gcn = (const float*)d_in[3];
    const float* Wq = (const float*)d_in[4],  *bq = (const float*)d_in[5];
    const float* Wk = (const float*)d_in[6],  *bk = (const float*)d_in[7];
    const float* Wv = (const float*)d_in[8],  *bv = (const float*)d_in[9];
    const float* Ws = (const float*)d_in[10], *bs = (const float*)d_in[11];
    float* out = (float*)d_out;

    k_init<<<(N_NODES + 255) / 256, 256>>>();
    k_hist<<<(E_EDGES + 255) / 256, 256>>>(ei);
    k_scan<<<1, 1024>>>();
    k_csr<<<(E_EDGES + 255) / 256, 256>>>(ei);

    k_convBW<<<(H_MID * F_IN + 255) / 256, 256>>>(W_gcn);
    k_packB2<<<(QKVS * H_MID + 255) / 256, 256>>>(Wq, Wk, Wv, Ws, bq, bk, bv, bs);

    // g = (x @ W_gcn) * dinv[row]  (in-kernel fp32->bf16 split of x)
    k_mmagemm<0><<<dim3(M_TILES, 2), 256>>>(x);

    k_agg<<<N_NODES, H_MID>>>(b_gcn);

    // qkvs = h @ Wcat + bcat
    k_mmagemm<1><<<dim3(M_TILES, 4), 256>>>(nullptr);

    k_alpha_stats<<<STAT_BLOCKS, 256>>>(ei);
    k_finalize<<<1, STAT_BLOCKS>>>();
    k_out<<<N_NODES, D_OUT>>>(out);
}

// round 9
// speedup vs baseline: 1.0218x; 1.0218x over previous
#include <cuda_runtime.h>
#include <cuda_bf16.h>
#include <math.h>
#include <stdint.h>

#define N_NODES 20000
#define E_EDGES 320000
#define F_IN    1024
#define H_MID   256
#define D_OUT   128
#define QKVS    512
#define STAT_BLOCKS 512
#define M_TILES ((N_NODES + 127) / 128)

// ---------------- scratch (static device globals; no allocations) ----------------
__device__ __align__(16) float  g_g[(size_t)N_NODES * H_MID];
__device__ __align__(16) float  g_qkvs[(size_t)N_NODES * QKVS];
__device__ __align__(16) float  g_alpha[E_EDGES];
__device__ float  g_dinv[N_NODES];
__device__ int    g_degcnt[N_NODES];
__device__ int    g_fill[N_NODES];
__device__ int    g_rowptr[N_NODES + 1];
__device__ int    g_csrc[E_EDGES];
__device__ int    g_ceid[E_EDGES];
__device__ double g_part[STAT_BLOCKS][2];
__device__ float  g_stats[2];
__device__ __align__(16) float  g_bcat[QKVS];
// bf16 split operands
__device__ __align__(16) __nv_bfloat16 g_Ahi[(size_t)N_NODES * F_IN];
__device__ __align__(16) __nv_bfloat16 g_Alo[(size_t)N_NODES * F_IN];
__device__ __align__(16) __nv_bfloat16 g_B1hi[(size_t)H_MID * F_IN];   // W_gcn^T [256][1024]
__device__ __align__(16) __nv_bfloat16 g_B1lo[(size_t)H_MID * F_IN];
__device__ __align__(16) __nv_bfloat16 g_Hhi[(size_t)N_NODES * H_MID]; // split h (from k_agg)
__device__ __align__(16) __nv_bfloat16 g_Hlo[(size_t)N_NODES * H_MID];
__device__ __align__(16) __nv_bfloat16 g_B2hi[(size_t)QKVS * H_MID];   // Wcat^T [512][256]
__device__ __align__(16) __nv_bfloat16 g_B2lo[(size_t)QKVS * H_MID];

// ---------------- helpers ----------------
__device__ __forceinline__ uint32_t smem_u32(const void* p) {
    uint32_t a;
    asm("{ .reg .u64 t; cvta.to.shared.u64 t, %1; cvt.u32.u64 %0, t; }" : "=r"(a) : "l"(p));
    return a;
}
__device__ __forceinline__ void mma16816(float* c, const uint32_t* a, const uint32_t* b) {
    asm volatile(
        "mma.sync.aligned.m16n8k16.row.col.f32.bf16.bf16.f32 "
        "{%0,%1,%2,%3}, {%4,%5,%6,%7}, {%8,%9}, {%0,%1,%2,%3};"
        : "+f"(c[0]), "+f"(c[1]), "+f"(c[2]), "+f"(c[3])
        : "r"(a[0]), "r"(a[1]), "r"(a[2]), "r"(a[3]), "r"(b[0]), "r"(b[1]));
}
__device__ __forceinline__ void ldm4(uint32_t* r, uint32_t addr) {
    asm volatile("ldmatrix.sync.aligned.m8n8.x4.shared.b16 {%0,%1,%2,%3}, [%4];"
        : "=r"(r[0]), "=r"(r[1]), "=r"(r[2]), "=r"(r[3]) : "r"(addr) : "memory");
}
__device__ __forceinline__ void split2(float a, float b, __nv_bfloat162& h, __nv_bfloat162& l) {
    __nv_bfloat16 ha = __float2bfloat16_rn(a);
    __nv_bfloat16 hb = __float2bfloat16_rn(b);
    h.x = ha; h.y = hb;
    l.x = __float2bfloat16_rn(a - __bfloat162float(ha));
    l.y = __float2bfloat16_rn(b - __bfloat162float(hb));
}

// ---------------- CSR build ----------------
__global__ void k_init() {
    int i = blockIdx.x * blockDim.x + threadIdx.x;
    if (i < N_NODES) { g_degcnt[i] = 0; g_fill[i] = 0; }
}

__global__ void k_hist(const int* __restrict__ ei) {
    int e = blockIdx.x * blockDim.x + threadIdx.x;
    if (e < E_EDGES) atomicAdd(&g_degcnt[ei[E_EDGES + e]], 1);
}

__global__ void k_scan() {
    const int n = N_NODES;
    const int PER = 20;
    __shared__ int wsum[32];
    int tid = threadIdx.x, lane = tid & 31, wid = tid >> 5;
    int start = tid * PER;
    int cnt[PER];
    int local = 0;
#pragma unroll
    for (int u = 0; u < PER; u++) {
        int i = start + u;
        int c = (i < n) ? g_degcnt[i] : 0;
        cnt[u] = c; local += c;
    }
    int v = local;
#pragma unroll
    for (int d = 1; d < 32; d <<= 1) { int t = __shfl_up_sync(0xffffffffu, v, d); if (lane >= d) v += t; }
    if (lane == 31) wsum[wid] = v;
    __syncthreads();
    if (wid == 0) {
        int w = wsum[lane];
#pragma unroll
        for (int d = 1; d < 32; d <<= 1) { int t = __shfl_up_sync(0xffffffffu, w, d); if (lane >= d) w += t; }
        wsum[lane] = w;
    }
    __syncthreads();
    int excl = (v - local) + (wid > 0 ? wsum[wid - 1] : 0);
    int run = excl;
#pragma unroll
    for (int u = 0; u < PER; u++) {
        int i = start + u;
        if (i < n) {
            g_rowptr[i] = run;
            g_dinv[i] = rsqrtf((float)(cnt[u] + 1));
        }
        run += cnt[u];
    }
    if (tid == 1023) g_rowptr[n] = run;
}

__global__ void k_csr(const int* __restrict__ ei) {
    int e = blockIdx.x * blockDim.x + threadIdx.x;
    if (e < E_EDGES) {
        int s = ei[e];
        int d = ei[E_EDGES + e];
        int pos = g_rowptr[d] + atomicAdd(&g_fill[d], 1);
        g_csrc[pos] = s;
        g_ceid[pos] = e;
    }
}

// ---------------- conversions ----------------
__global__ void k_convA(const float* __restrict__ X) {
    size_t i = (size_t)blockIdx.x * 256 + threadIdx.x;
    if (i >= (size_t)N_NODES * F_IN / 4) return;
    float4 v = ((const float4*)X)[i];
    __nv_bfloat162 h0, l0, h1, l1;
    split2(v.x, v.y, h0, l0);
    split2(v.z, v.w, h1, l1);
    ((__nv_bfloat162*)g_Ahi)[2 * i] = h0;
    ((__nv_bfloat162*)g_Ahi)[2 * i + 1] = h1;
    ((__nv_bfloat162*)g_Alo)[2 * i] = l0;
    ((__nv_bfloat162*)g_Alo)[2 * i + 1] = l1;
}

// W_gcn[1024,256] -> B1 [256][1024]
__global__ void k_convBW(const float* __restrict__ Wg) {
    int idx = blockIdx.x * blockDim.x + threadIdx.x;
    if (idx >= H_MID * F_IN) return;
    int n = idx >> 10, k = idx & 1023;
    float v = Wg[(size_t)k * H_MID + n];
    __nv_bfloat16 h = __float2bfloat16_rn(v);
    g_B1hi[idx] = h;
    g_B1lo[idx] = __float2bfloat16_rn(v - __bfloat162float(h));
}

// Wq|Wk|Wv|Ws [256,128] -> B2 [512][256] + bcat
__global__ void k_packB2(const float* __restrict__ Wq, const float* __restrict__ Wk,
                         const float* __restrict__ Wv, const float* __restrict__ Ws,
                         const float* __restrict__ bq, const float* __restrict__ bk,
                         const float* __restrict__ bv, const float* __restrict__ bs) {
    int idx = blockIdx.x * blockDim.x + threadIdx.x;
    if (idx >= QKVS * H_MID) return;
    int n = idx >> 8, k = idx & 255;
    int w = n >> 7, c = n & 127;
    const float* W = (w == 0) ? Wq : (w == 1) ? Wk : (w == 2) ? Wv : Ws;
    float v = W[(size_t)k * D_OUT + c];
    __nv_bfloat16 h = __float2bfloat16_rn(v);
    g_B2hi[idx] = h;
    g_B2lo[idx] = __float2bfloat16_rn(v - __bfloat162float(h));
    if (idx < QKVS) {
        int nn = idx, ww = nn >> 7, cc = nn & 127;
        const float* b = (ww == 0) ? bq : (ww == 1) ? bk : (ww == 2) ? bv : bs;
        g_bcat[nn] = b[cc];
    }
}

// ---------------- split-bf16 GEMM via mma.sync (R7-proven structure) ----------------
// MODE 0: g_g = (x @ W_gcn) * dinv[row]   A=g_Ahi/lo [N][1024], B=g_B1 [256][1024]
// MODE 1: g_qkvs = h @ Wcat + bcat        A=g_Hhi/lo [N][256],  B=g_B2 [512][256]
#define SPAD 24

template <int MODE>
__global__ __launch_bounds__(256)
void k_mmagemm() {
    const int K_TOT = (MODE == 0) ? F_IN : H_MID;
    const __nv_bfloat16* Ahi = (MODE == 0) ? g_Ahi : g_Hhi;
    const __nv_bfloat16* Alo = (MODE == 0) ? g_Alo : g_Hlo;
    const __nv_bfloat16* Bhi = (MODE == 0) ? g_B1hi : g_B2hi;
    const __nv_bfloat16* Blo = (MODE == 0) ? g_B1lo : g_B2lo;

    __shared__ __align__(16) __nv_bfloat16 sAh[128 * SPAD], sAl[128 * SPAD];
    __shared__ __align__(16) __nv_bfloat16 sBh[128 * SPAD], sBl[128 * SPAD];

    int tid = threadIdx.x, wid = tid >> 5, lane = tid & 31;
    int m0 = blockIdx.x * 128, n0 = blockIdx.y * 128;
    int wm = wid & 3, wn = wid >> 2;

    int lrow = tid >> 1, lhalf = (tid & 1) << 3;
    const int NCH = K_TOT / 16;
    int arow = m0 + lrow;
    bool aok = arow < N_NODES;
    const __nv_bfloat16* pAh = Ahi + (size_t)arow * K_TOT + lhalf;
    const __nv_bfloat16* pAl = Alo + (size_t)arow * K_TOT + lhalf;
    const __nv_bfloat16* pBh = Bhi + (size_t)(n0 + lrow) * K_TOT + lhalf;
    const __nv_bfloat16* pBl = Blo + (size_t)(n0 + lrow) * K_TOT + lhalf;

    uint4 z4 = make_uint4(0, 0, 0, 0);
    uint4 vah = aok ? *(const uint4*)pAh : z4;
    uint4 val_ = aok ? *(const uint4*)pAl : z4;
    uint4 vbh = *(const uint4*)pBh;
    uint4 vbl = *(const uint4*)pBl;

    float acc[2][8][4];
#pragma unroll
    for (int a = 0; a < 2; a++)
#pragma unroll
        for (int b = 0; b < 8; b++)
#pragma unroll
            for (int c = 0; c < 4; c++) acc[a][b][c] = 0.f;

    uint32_t baseAh = smem_u32(sAh), baseAl = smem_u32(sAl);
    uint32_t baseBh = smem_u32(sBh), baseBl = smem_u32(sBl);
    int soff = lrow * SPAD + lhalf;

    int g8 = lane >> 3, w8 = lane & 7;
    uint32_t a_off = (uint32_t)((((((g8 & 1) << 3) + w8) + wm * 32) * SPAD + ((g8 >> 1) << 3)) * 2);
    uint32_t b_off = (uint32_t)((((((g8 >> 1) << 3) + w8) + wn * 64) * SPAD + ((g8 & 1) << 3)) * 2);

    for (int c = 0; c < NCH; c++) {
        *(uint4*)&sAh[soff] = vah;
        *(uint4*)&sAl[soff] = val_;
        *(uint4*)&sBh[soff] = vbh;
        *(uint4*)&sBl[soff] = vbl;
        __syncthreads();
        if (c + 1 < NCH) {
            int k0 = (c + 1) * 16;
            vah = aok ? *(const uint4*)(pAh + k0) : z4;
            val_ = aok ? *(const uint4*)(pAl + k0) : z4;
            vbh = *(const uint4*)(pBh + k0);
            vbl = *(const uint4*)(pBl + k0);
        }
        uint32_t ah[2][4], al[2][4], bh[4][4], bl[4][4];
#pragma unroll
        for (int mb = 0; mb < 2; mb++) {
            ldm4(ah[mb], baseAh + a_off + mb * 16 * SPAD * 2);
            ldm4(al[mb], baseAl + a_off + mb * 16 * SPAD * 2);
        }
#pragma unroll
        for (int q = 0; q < 4; q++) {
            ldm4(bh[q], baseBh + b_off + q * 16 * SPAD * 2);
            ldm4(bl[q], baseBl + b_off + q * 16 * SPAD * 2);
        }
#pragma unroll
        for (int mb = 0; mb < 2; mb++)
#pragma unroll
            for (int q = 0; q < 4; q++)
#pragma unroll
                for (int hh = 0; hh < 2; hh++) {
                    float* ca = acc[mb][q * 2 + hh];
                    mma16816(ca, ah[mb], &bh[q][hh * 2]);
                    mma16816(ca, al[mb], &bh[q][hh * 2]);
                    mma16816(ca, ah[mb], &bl[q][hh * 2]);
                }
        __syncthreads();
    }

    const int CS = (MODE == 0) ? H_MID : QKVS;
    float* Cp = (MODE == 0) ? g_g : g_qkvs;
#pragma unroll
    for (int mb = 0; mb < 2; mb++) {
        int rbase = m0 + wm * 32 + mb * 16 + (lane >> 2);
#pragma unroll
        for (int hf = 0; hf < 2; hf++) {
            int r = rbase + hf * 8;
            if (r >= N_NODES) continue;
            float rs = (MODE == 0) ? g_dinv[r] : 1.f;
#pragma unroll
            for (int n8 = 0; n8 < 8; n8++) {
                int col = n0 + wn * 64 + n8 * 8 + ((lane & 3) << 1);
                float v0 = acc[mb][n8][hf * 2 + 0];
                float v1 = acc[mb][n8][hf * 2 + 1];
                if (MODE == 0) { v0 *= rs; v1 *= rs; }
                else { v0 += g_bcat[col]; v1 += g_bcat[col + 1]; }
                float2 o; o.x = v0; o.y = v1;
                *(float2*)(Cp + (size_t)r * CS + col) = o;
            }
        }
    }
}

// ---------------- GCN aggregation: 4-way MLP unroll; writes bf16 hi/lo split ----------------
__global__ __launch_bounds__(H_MID)
void k_agg(const float* __restrict__ b_gcn) {
    int i = blockIdx.x;
    int f = threadIdx.x;
    float a0 = g_g[(size_t)i * H_MID + f];    // self loop
    float a1 = 0.f, a2 = 0.f, a3 = 0.f;
    __shared__ int sj[H_MID];
    int s0 = g_rowptr[i], e0 = g_rowptr[i + 1];
    for (int base = s0; base < e0; base += H_MID) {
        int cnt = min(H_MID, e0 - base);
        if (f < cnt) sj[f] = g_csrc[base + f];
        __syncthreads();
        int p = 0;
        for (; p + 4 <= cnt; p += 4) {
            float v0 = g_g[(size_t)sj[p + 0] * H_MID + f];
            float v1 = g_g[(size_t)sj[p + 1] * H_MID + f];
            float v2 = g_g[(size_t)sj[p + 2] * H_MID + f];
            float v3 = g_g[(size_t)sj[p + 3] * H_MID + f];
            a0 += v0; a1 += v1; a2 += v2; a3 += v3;
        }
        for (; p < cnt; p++)
            a0 += g_g[(size_t)sj[p] * H_MID + f];
        __syncthreads();
    }
    float acc = (a0 + a1) + (a2 + a3);
    float v = g_dinv[i] * acc + b_gcn[f];
    v = (v >= 0.f) ? v : 0.01f * v;
    __nv_bfloat16 h = __float2bfloat16_rn(v);
    g_Hhi[(size_t)i * H_MID + f] = h;
    g_Hlo[(size_t)i * H_MID + f] = __float2bfloat16_rn(v - __bfloat162float(h));
}

// ---------------- fused attention logits + partial stats ----------------
__global__ __launch_bounds__(256)
void k_alpha_stats(const int* __restrict__ ei) {
    int wid = threadIdx.x >> 5, lane = threadIdx.x & 31;
    double s = 0.0, s2 = 0.0;
    for (int e = blockIdx.x * 8 + wid; e < E_EDGES; e += STAT_BLOCKS * 8) {
        int sn = ei[e], d = ei[E_EDGES + e];
        const float4* q = (const float4*)(g_qkvs + (size_t)d * QKVS);
        const float4* k = (const float4*)(g_qkvs + (size_t)sn * QKVS + D_OUT);
        float4 a = q[lane], b = k[lane];
        float p = a.x * b.x + a.y * b.y + a.z * b.z + a.w * b.w;
#pragma unroll
        for (int o = 16; o; o >>= 1) p += __shfl_xor_sync(0xffffffffu, p, o);
        if (lane == 0) {
            float v = p * 0.08838834764831845f;   // 1/sqrt(128)
            g_alpha[e] = v;
            s += (double)v;
            s2 += (double)v * (double)v;
        }
    }
#pragma unroll
    for (int o = 16; o; o >>= 1) {
        s  += __shfl_down_sync(0xffffffffu, s,  o);
        s2 += __shfl_down_sync(0xffffffffu, s2, o);
    }
    __shared__ double ws[8], ws2[8];
    if (lane == 0) { ws[wid] = s; ws2[wid] = s2; }
    __syncthreads();
    if (threadIdx.x == 0) {
        double ts = 0.0, ts2 = 0.0;
        for (int w = 0; w < 8; w++) { ts += ws[w]; ts2 += ws2[w]; }
        g_part[blockIdx.x][0] = ts;
        g_part[blockIdx.x][1] = ts2;
    }
}

__global__ __launch_bounds__(STAT_BLOCKS)
void k_finalize() {
    int t = threadIdx.x;
    double s = g_part[t][0], s2 = g_part[t][1];
#pragma unroll
    for (int o = 16; o; o >>= 1) {
        s  += __shfl_down_sync(0xffffffffu, s,  o);
        s2 += __shfl_down_sync(0xffffffffu, s2, o);
    }
    __shared__ double ws[16], ws2[16];
    int lane = t & 31, wid = t >> 5;
    if (lane == 0) { ws[wid] = s; ws2[wid] = s2; }
    __syncthreads();
    if (t == 0) {
        double ts = 0.0, ts2 = 0.0;
        for (int w = 0; w < STAT_BLOCKS / 32; w++) { ts += ws[w]; ts2 += ws2[w]; }
        double En = (double)E_EDGES;
        double mean = ts / En;
        double var = (ts2 - En * mean * mean) / (En - 1.0);   // ddof=1
        g_stats[0] = (float)mean;
        g_stats[1] = (float)(3.0 / sqrt(var));                // SCALE_PARAM/std
    }
}

// ---------------- output: 4-way MLP unroll ----------------
__global__ __launch_bounds__(D_OUT)
void k_out(float* __restrict__ out) {
    int i = blockIdx.x;
    int f = threadIdx.x;
    float mean = g_stats[0], sc = g_stats[1];
    float a0 = g_qkvs[(size_t)i * QKVS + 384 + f];   // skip s = h@Ws + bs
    float a1 = 0.f, a2 = 0.f, a3 = 0.f;
    __shared__ int   sj[D_OUT];
    __shared__ float sa[D_OUT];
    int s0 = g_rowptr[i], e0 = g_rowptr[i + 1];
    for (int base = s0; base < e0; base += D_OUT) {
        int cnt = min(D_OUT, e0 - base);
        if (f < cnt) {
            sj[f] = g_csrc[base + f];
            float a = (g_alpha[g_ceid[base + f]] - mean) * sc;
            sa[f] = 1.0f / (1.0f + expf(-a));
        }
        __syncthreads();
        int p = 0;
        for (; p + 4 <= cnt; p += 4) {
            float v0 = g_qkvs[(size_t)sj[p + 0] * QKVS + 256 + f];
            float v1 = g_qkvs[(size_t)sj[p + 1] * QKVS + 256 + f];
            float v2 = g_qkvs[(size_t)sj[p + 2] * QKVS + 256 + f];
            float v3 = g_qkvs[(size_t)sj[p + 3] * QKVS + 256 + f];
            a0 += v0 * sa[p + 0];
            a1 += v1 * sa[p + 1];
            a2 += v2 * sa[p + 2];
            a3 += v3 * sa[p + 3];
        }
        for (; p < cnt; p++)
            a0 += g_qkvs[(size_t)sj[p] * QKVS + 256 + f] * sa[p];
        __syncthreads();
    }
    out[(size_t)i * D_OUT + f] = (a0 + a1) + (a2 + a3);
}

// ---------------- launch ----------------
extern "C" void kernel_launch(void* const* d_in, const int* in_sizes, int n_in,
                              void* d_out, int out_size) {
    (void)in_sizes; (void)n_in; (void)out_size;
    const float* x     = (const float*)d_in[0];
    const int*   ei    = (const int*)d_in[1];
    const float* W_gcn = (const float*)d_in[2];
    const float* b_gcn = (const float*)d_in[3];
    const float* Wq = (const float*)d_in[4],  *bq = (const float*)d_in[5];
    const float* Wk = (const float*)d_in[6],  *bk = (const float*)d_in[7];
    const float* Wv = (const float*)d_in[8],  *bv = (const float*)d_in[9];
    const float* Ws = (const float*)d_in[10], *bs = (const float*)d_in[11];
    float* out = (float*)d_out;

    k_init<<<(N_NODES + 255) / 256, 256>>>();
    k_hist<<<(E_EDGES + 255) / 256, 256>>>(ei);
    k_scan<<<1, 1024>>>();
    k_csr<<<(E_EDGES + 255) / 256, 256>>>(ei);

    k_convA<<<(int)(((size_t)N_NODES * F_IN / 4 + 255) / 256), 256>>>(x);
    k_convBW<<<(H_MID * F_IN + 255) / 256, 256>>>(W_gcn);
    k_packB2<<<(QKVS * H_MID + 255) / 256, 256>>>(Wq, Wk, Wv, Ws, bq, bk, bv, bs);

    // g = (x @ W_gcn) * dinv[row]
    k_mmagemm<0><<<dim3(M_TILES, 2), 256>>>();

    k_agg<<<N_NODES, H_MID>>>(b_gcn);

    // qkvs = h @ Wcat + bcat
    k_mmagemm<1><<<dim3(M_TILES, 4), 256>>>();

    k_alpha_stats<<<STAT_BLOCKS, 256>>>(ei);
    k_finalize<<<1, STAT_BLOCKS>>>();
    k_out<<<N_NODES, D_OUT>>>(out);
}

// round 10
// speedup vs baseline: 1.1369x; 1.1126x over previous
#include <cuda_runtime.h>
#include <cuda_bf16.h>
#include <math.h>
#include <stdint.h>

#define N_NODES 20000
#define E_EDGES 320000
#define F_IN    1024
#define H_MID   256
#define D_OUT   128
#define QKVS    512
#define STAT_BLOCKS 256
#define M_TILES ((N_NODES + 127) / 128)

// ---------------- scratch (static device globals; no allocations) ----------------
__device__ __align__(16) float  g_g[(size_t)N_NODES * H_MID];
__device__ __align__(16) float  g_qkvs[(size_t)N_NODES * QKVS];
__device__ __align__(16) float  g_alpha[E_EDGES];
__device__ float  g_dinv[N_NODES];
__device__ int    g_degcnt[N_NODES];
__device__ int    g_fill[N_NODES];
__device__ int    g_rowptr[N_NODES + 1];
__device__ int    g_csrc[E_EDGES];
__device__ int    g_ceid[E_EDGES];
__device__ double g_part[STAT_BLOCKS][2];
__device__ float  g_stats[2];
__device__ __align__(16) float  g_bcat[QKVS];
// bf16 split operands
__device__ __align__(16) __nv_bfloat16 g_Ahi[(size_t)N_NODES * F_IN];
__device__ __align__(16) __nv_bfloat16 g_Alo[(size_t)N_NODES * F_IN];
__device__ __align__(16) __nv_bfloat16 g_B1hi[(size_t)H_MID * F_IN];   // W_gcn^T [256][1024]
__device__ __align__(16) __nv_bfloat16 g_B1lo[(size_t)H_MID * F_IN];
__device__ __align__(16) __nv_bfloat16 g_Hhi[(size_t)N_NODES * H_MID]; // split h
__device__ __align__(16) __nv_bfloat16 g_Hlo[(size_t)N_NODES * H_MID];
__device__ __align__(16) __nv_bfloat16 g_B2hi[(size_t)QKVS * H_MID];   // Wcat^T [512][256]
__device__ __align__(16) __nv_bfloat16 g_B2lo[(size_t)QKVS * H_MID];

// ---------------- helpers ----------------
__device__ __forceinline__ uint32_t smem_u32(const void* p) {
    uint32_t a;
    asm("{ .reg .u64 t; cvta.to.shared.u64 t, %1; cvt.u32.u64 %0, t; }" : "=r"(a) : "l"(p));
    return a;
}
__device__ __forceinline__ void mma16816(float* c, const uint32_t* a, const uint32_t* b) {
    asm volatile(
        "mma.sync.aligned.m16n8k16.row.col.f32.bf16.bf16.f32 "
        "{%0,%1,%2,%3}, {%4,%5,%6,%7}, {%8,%9}, {%0,%1,%2,%3};"
        : "+f"(c[0]), "+f"(c[1]), "+f"(c[2]), "+f"(c[3])
        : "r"(a[0]), "r"(a[1]), "r"(a[2]), "r"(a[3]), "r"(b[0]), "r"(b[1]));
}
__device__ __forceinline__ void ldm4(uint32_t* r, uint32_t addr) {
    asm volatile("ldmatrix.sync.aligned.m8n8.x4.shared.b16 {%0,%1,%2,%3}, [%4];"
        : "=r"(r[0]), "=r"(r[1]), "=r"(r[2]), "=r"(r[3]) : "r"(addr) : "memory");
}
__device__ __forceinline__ void split2(float a, float b, __nv_bfloat162& h, __nv_bfloat162& l) {
    __nv_bfloat16 ha = __float2bfloat16_rn(a);
    __nv_bfloat16 hb = __float2bfloat16_rn(b);
    h.x = ha; h.y = hb;
    l.x = __float2bfloat16_rn(a - __bfloat162float(ha));
    l.y = __float2bfloat16_rn(b - __bfloat162float(hb));
}

// ---------------- CSR build ----------------
__global__ void k_init() {
    int i = blockIdx.x * blockDim.x + threadIdx.x;
    if (i < N_NODES) { g_degcnt[i] = 0; g_fill[i] = 0; }
}

__global__ void k_hist(const int* __restrict__ ei) {
    int e = blockIdx.x * blockDim.x + threadIdx.x;
    if (e < E_EDGES) atomicAdd(&g_degcnt[ei[E_EDGES + e]], 1);
}

__global__ void k_scan() {
    const int n = N_NODES;
    const int PER = 20;
    __shared__ int wsum[32];
    int tid = threadIdx.x, lane = tid & 31, wid = tid >> 5;
    int start = tid * PER;
    int cnt[PER];
    int local = 0;
#pragma unroll
    for (int u = 0; u < PER; u++) {
        int i = start + u;
        int c = (i < n) ? g_degcnt[i] : 0;
        cnt[u] = c; local += c;
    }
    int v = local;
#pragma unroll
    for (int d = 1; d < 32; d <<= 1) { int t = __shfl_up_sync(0xffffffffu, v, d); if (lane >= d) v += t; }
    if (lane == 31) wsum[wid] = v;
    __syncthreads();
    if (wid == 0) {
        int w = wsum[lane];
#pragma unroll
        for (int d = 1; d < 32; d <<= 1) { int t = __shfl_up_sync(0xffffffffu, w, d); if (lane >= d) w += t; }
        wsum[lane] = w;
    }
    __syncthreads();
    int excl = (v - local) + (wid > 0 ? wsum[wid - 1] : 0);
    int run = excl;
#pragma unroll
    for (int u = 0; u < PER; u++) {
        int i = start + u;
        if (i < n) {
            g_rowptr[i] = run;
            g_dinv[i] = rsqrtf((float)(cnt[u] + 1));
        }
        run += cnt[u];
    }
    if (tid == 1023) g_rowptr[n] = run;
}

__global__ void k_csr(const int* __restrict__ ei) {
    int e = blockIdx.x * blockDim.x + threadIdx.x;
    if (e < E_EDGES) {
        int s = ei[e];
        int d = ei[E_EDGES + e];
        int pos = g_rowptr[d] + atomicAdd(&g_fill[d], 1);
        g_csrc[pos] = s;
        g_ceid[pos] = e;
    }
}

// ---------------- conversions ----------------
__global__ void k_convA(const float* __restrict__ X) {
    size_t i = (size_t)blockIdx.x * 256 + threadIdx.x;
    if (i >= (size_t)N_NODES * F_IN / 4) return;
    float4 v = ((const float4*)X)[i];
    __nv_bfloat162 h0, l0, h1, l1;
    split2(v.x, v.y, h0, l0);
    split2(v.z, v.w, h1, l1);
    ((__nv_bfloat162*)g_Ahi)[2 * i] = h0;
    ((__nv_bfloat162*)g_Ahi)[2 * i + 1] = h1;
    ((__nv_bfloat162*)g_Alo)[2 * i] = l0;
    ((__nv_bfloat162*)g_Alo)[2 * i + 1] = l1;
}

// W_gcn[1024,256] -> B1 [256][1024]
__global__ void k_convBW(const float* __restrict__ Wg) {
    int idx = blockIdx.x * blockDim.x + threadIdx.x;
    if (idx >= H_MID * F_IN) return;
    int n = idx >> 10, k = idx & 1023;
    float v = Wg[(size_t)k * H_MID + n];
    __nv_bfloat16 h = __float2bfloat16_rn(v);
    g_B1hi[idx] = h;
    g_B1lo[idx] = __float2bfloat16_rn(v - __bfloat162float(h));
}

// Wq|Wk|Wv|Ws [256,128] -> B2 [512][256] + bcat
__global__ void k_packB2(const float* __restrict__ Wq, const float* __restrict__ Wk,
                         const float* __restrict__ Wv, const float* __restrict__ Ws,
                         const float* __restrict__ bq, const float* __restrict__ bk,
                         const float* __restrict__ bv, const float* __restrict__ bs) {
    int idx = blockIdx.x * blockDim.x + threadIdx.x;
    if (idx >= QKVS * H_MID) return;
    int n = idx >> 8, k = idx & 255;
    int w = n >> 7, c = n & 127;
    const float* W = (w == 0) ? Wq : (w == 1) ? Wk : (w == 2) ? Wv : Ws;
    float v = W[(size_t)k * D_OUT + c];
    __nv_bfloat16 h = __float2bfloat16_rn(v);
    g_B2hi[idx] = h;
    g_B2lo[idx] = __float2bfloat16_rn(v - __bfloat162float(h));
    if (idx < QKVS) {
        int nn = idx, ww = nn >> 7, cc = nn & 127;
        const float* b = (ww == 0) ? bq : (ww == 1) ? bk : (ww == 2) ? bv : bs;
        g_bcat[nn] = b[cc];
    }
}

// ---------------- split-bf16 GEMM via mma.sync (R7-proven, untouched) ----------------
#define SPAD 24

template <int MODE>
__global__ __launch_bounds__(256)
void k_mmagemm() {
    const int K_TOT = (MODE == 0) ? F_IN : H_MID;
    const __nv_bfloat16* Ahi = (MODE == 0) ? g_Ahi : g_Hhi;
    const __nv_bfloat16* Alo = (MODE == 0) ? g_Alo : g_Hlo;
    const __nv_bfloat16* Bhi = (MODE == 0) ? g_B1hi : g_B2hi;
    const __nv_bfloat16* Blo = (MODE == 0) ? g_B1lo : g_B2lo;

    __shared__ __align__(16) __nv_bfloat16 sAh[128 * SPAD], sAl[128 * SPAD];
    __shared__ __align__(16) __nv_bfloat16 sBh[128 * SPAD], sBl[128 * SPAD];

    int tid = threadIdx.x, wid = tid >> 5, lane = tid & 31;
    int m0 = blockIdx.x * 128, n0 = blockIdx.y * 128;
    int wm = wid & 3, wn = wid >> 2;

    int lrow = tid >> 1, lhalf = (tid & 1) << 3;
    const int NCH = K_TOT / 16;
    int arow = m0 + lrow;
    bool aok = arow < N_NODES;
    const __nv_bfloat16* pAh = Ahi + (size_t)arow * K_TOT + lhalf;
    const __nv_bfloat16* pAl = Alo + (size_t)arow * K_TOT + lhalf;
    const __nv_bfloat16* pBh = Bhi + (size_t)(n0 + lrow) * K_TOT + lhalf;
    const __nv_bfloat16* pBl = Blo + (size_t)(n0 + lrow) * K_TOT + lhalf;

    uint4 z4 = make_uint4(0, 0, 0, 0);
    uint4 vah = aok ? *(const uint4*)pAh : z4;
    uint4 val_ = aok ? *(const uint4*)pAl : z4;
    uint4 vbh = *(const uint4*)pBh;
    uint4 vbl = *(const uint4*)pBl;

    float acc[2][8][4];
#pragma unroll
    for (int a = 0; a < 2; a++)
#pragma unroll
        for (int b = 0; b < 8; b++)
#pragma unroll
            for (int c = 0; c < 4; c++) acc[a][b][c] = 0.f;

    uint32_t baseAh = smem_u32(sAh), baseAl = smem_u32(sAl);
    uint32_t baseBh = smem_u32(sBh), baseBl = smem_u32(sBl);
    int soff = lrow * SPAD + lhalf;

    int g8 = lane >> 3, w8 = lane & 7;
    uint32_t a_off = (uint32_t)((((((g8 & 1) << 3) + w8) + wm * 32) * SPAD + ((g8 >> 1) << 3)) * 2);
    uint32_t b_off = (uint32_t)((((((g8 >> 1) << 3) + w8) + wn * 64) * SPAD + ((g8 & 1) << 3)) * 2);

    for (int c = 0; c < NCH; c++) {
        *(uint4*)&sAh[soff] = vah;
        *(uint4*)&sAl[soff] = val_;
        *(uint4*)&sBh[soff] = vbh;
        *(uint4*)&sBl[soff] = vbl;
        __syncthreads();
        if (c + 1 < NCH) {
            int k0 = (c + 1) * 16;
            vah = aok ? *(const uint4*)(pAh + k0) : z4;
            val_ = aok ? *(const uint4*)(pAl + k0) : z4;
            vbh = *(const uint4*)(pBh + k0);
            vbl = *(const uint4*)(pBl + k0);
        }
        uint32_t ah[2][4], al[2][4], bh[4][4], bl[4][4];
#pragma unroll
        for (int mb = 0; mb < 2; mb++) {
            ldm4(ah[mb], baseAh + a_off + mb * 16 * SPAD * 2);
            ldm4(al[mb], baseAl + a_off + mb * 16 * SPAD * 2);
        }
#pragma unroll
        for (int q = 0; q < 4; q++) {
            ldm4(bh[q], baseBh + b_off + q * 16 * SPAD * 2);
            ldm4(bl[q], baseBl + b_off + q * 16 * SPAD * 2);
        }
#pragma unroll
        for (int mb = 0; mb < 2; mb++)
#pragma unroll
            for (int q = 0; q < 4; q++)
#pragma unroll
                for (int hh = 0; hh < 2; hh++) {
                    float* ca = acc[mb][q * 2 + hh];
                    mma16816(ca, ah[mb], &bh[q][hh * 2]);
                    mma16816(ca, al[mb], &bh[q][hh * 2]);
                    mma16816(ca, ah[mb], &bl[q][hh * 2]);
                }
        __syncthreads();
    }

    const int CS = (MODE == 0) ? H_MID : QKVS;
    float* Cp = (MODE == 0) ? g_g : g_qkvs;
#pragma unroll
    for (int mb = 0; mb < 2; mb++) {
        int rbase = m0 + wm * 32 + mb * 16 + (lane >> 2);
#pragma unroll
        for (int hf = 0; hf < 2; hf++) {
            int r = rbase + hf * 8;
            if (r >= N_NODES) continue;
            float rs = (MODE == 0) ? g_dinv[r] : 1.f;
#pragma unroll
            for (int n8 = 0; n8 < 8; n8++) {
                int col = n0 + wn * 64 + n8 * 8 + ((lane & 3) << 1);
                float v0 = acc[mb][n8][hf * 2 + 0];
                float v1 = acc[mb][n8][hf * 2 + 1];
                if (MODE == 0) { v0 *= rs; v1 *= rs; }
                else { v0 += g_bcat[col]; v1 += g_bcat[col + 1]; }
                float2 o; o.x = v0; o.y = v1;
                *(float2*)(Cp + (size_t)r * CS + col) = o;
            }
        }
    }
}

// ---------------- GCN aggregation: float2/thread, 4-way MLP unroll, split write ----------------
__global__ __launch_bounds__(128)
void k_agg(const float* __restrict__ b_gcn) {
    int i = blockIdx.x;
    int f = threadIdx.x;                       // owns features 2f, 2f+1
    const float2* G = (const float2*)g_g;      // row stride 128 float2
    float2 a0 = G[(size_t)i * 128 + f];        // self loop
    float2 a1 = make_float2(0.f, 0.f), a2 = a1, a3 = a1;
    __shared__ int sj[128];
    int s0 = g_rowptr[i], e0 = g_rowptr[i + 1];
    for (int base = s0; base < e0; base += 128) {
        int cnt = min(128, e0 - base);
        if (f < cnt) sj[f] = g_csrc[base + f];
        __syncthreads();
        int p = 0;
        for (; p + 4 <= cnt; p += 4) {
            float2 v0 = G[(size_t)sj[p + 0] * 128 + f];
            float2 v1 = G[(size_t)sj[p + 1] * 128 + f];
            float2 v2 = G[(size_t)sj[p + 2] * 128 + f];
            float2 v3 = G[(size_t)sj[p + 3] * 128 + f];
            a0.x += v0.x; a0.y += v0.y;
            a1.x += v1.x; a1.y += v1.y;
            a2.x += v2.x; a2.y += v2.y;
            a3.x += v3.x; a3.y += v3.y;
        }
        for (; p < cnt; p++) {
            float2 v = G[(size_t)sj[p] * 128 + f];
            a0.x += v.x; a0.y += v.y;
        }
        __syncthreads();
    }
    float di = g_dinv[i];
    float2 bb = ((const float2*)b_gcn)[f];
    float vx = di * ((a0.x + a1.x) + (a2.x + a3.x)) + bb.x;
    float vy = di * ((a0.y + a1.y) + (a2.y + a3.y)) + bb.y;
    vx = (vx >= 0.f) ? vx : 0.01f * vx;
    vy = (vy >= 0.f) ? vy : 0.01f * vy;
    __nv_bfloat162 h, l;
    split2(vx, vy, h, l);
    ((__nv_bfloat162*)g_Hhi)[(size_t)i * 128 + f] = h;
    ((__nv_bfloat162*)g_Hlo)[(size_t)i * 128 + f] = l;
}

// ---------------- attention logits (R7 layout: warp per edge) ----------------
__global__ __launch_bounds__(256)
void k_alpha(const int* __restrict__ ei) {
    int warp = threadIdx.x >> 5, lane = threadIdx.x & 31;
    int e = blockIdx.x * 8 + warp;
    if (e >= E_EDGES) return;
    int s = ei[e], d = ei[E_EDGES + e];
    const float4* q = (const float4*)(g_qkvs + (size_t)d * QKVS);
    const float4* k = (const float4*)(g_qkvs + (size_t)s * QKVS + D_OUT);
    float4 a = q[lane], b = k[lane];
    float p = a.x * b.x + a.y * b.y + a.z * b.z + a.w * b.w;
#pragma unroll
    for (int o = 16; o; o >>= 1) p += __shfl_xor_sync(0xffffffffu, p, o);
    if (lane == 0) g_alpha[e] = p * 0.08838834764831845f;
}

__global__ __launch_bounds__(256)
void k_stats() {
    double s = 0.0, s2 = 0.0;
    for (int i = blockIdx.x * blockDim.x + threadIdx.x; i < E_EDGES; i += STAT_BLOCKS * 256) {
        double a = (double)g_alpha[i];
        s += a; s2 += a * a;
    }
#pragma unroll
    for (int o = 16; o; o >>= 1) {
        s  += __shfl_down_sync(0xffffffffu, s,  o);
        s2 += __shfl_down_sync(0xffffffffu, s2, o);
    }
    __shared__ double ws[8], ws2[8];
    int lane = threadIdx.x & 31, wid = threadIdx.x >> 5;
    if (lane == 0) { ws[wid] = s; ws2[wid] = s2; }
    __syncthreads();
    if (threadIdx.x == 0) {
        double ts = 0.0, ts2 = 0.0;
        for (int w = 0; w < 8; w++) { ts += ws[w]; ts2 += ws2[w]; }
        g_part[blockIdx.x][0] = ts;
        g_part[blockIdx.x][1] = ts2;
    }
}

__global__ __launch_bounds__(STAT_BLOCKS)
void k_finalize() {
    int t = threadIdx.x;
    double s = g_part[t][0], s2 = g_part[t][1];
#pragma unroll
    for (int o = 16; o; o >>= 1) {
        s  += __shfl_down_sync(0xffffffffu, s,  o);
        s2 += __shfl_down_sync(0xffffffffu, s2, o);
    }
    __shared__ double ws[8], ws2[8];
    int lane = t & 31, wid = t >> 5;
    if (lane == 0) { ws[wid] = s; ws2[wid] = s2; }
    __syncthreads();
    if (t == 0) {
        double ts = 0.0, ts2 = 0.0;
        for (int w = 0; w < STAT_BLOCKS / 32; w++) { ts += ws[w]; ts2 += ws2[w]; }
        double En = (double)E_EDGES;
        double mean = ts / En;
        double var = (ts2 - En * mean * mean) / (En - 1.0);   // ddof=1
        g_stats[0] = (float)mean;
        g_stats[1] = (float)(3.0 / sqrt(var));                // SCALE_PARAM/std
    }
}

// ---------------- output: 4-way MLP unroll ----------------
__global__ __launch_bounds__(D_OUT)
void k_out(float* __restrict__ out) {
    int i = blockIdx.x;
    int f = threadIdx.x;
    float mean = g_stats[0], sc = g_stats[1];
    float a0 = g_qkvs[(size_t)i * QKVS + 384 + f];   // skip s = h@Ws + bs
    float a1 = 0.f, a2 = 0.f, a3 = 0.f;
    __shared__ int   sj[D_OUT];
    __shared__ float sa[D_OUT];
    int s0 = g_rowptr[i], e0 = g_rowptr[i + 1];
    for (int base = s0; base < e0; base += D_OUT) {
        int cnt = min(D_OUT, e0 - base);
        if (f < cnt) {
            sj[f] = g_csrc[base + f];
            float a = (g_alpha[g_ceid[base + f]] - mean) * sc;
            sa[f] = 1.0f / (1.0f + expf(-a));
        }
        __syncthreads();
        int p = 0;
        for (; p + 4 <= cnt; p += 4) {
            float v0 = g_qkvs[(size_t)sj[p + 0] * QKVS + 256 + f];
            float v1 = g_qkvs[(size_t)sj[p + 1] * QKVS + 256 + f];
            float v2 = g_qkvs[(size_t)sj[p + 2] * QKVS + 256 + f];
            float v3 = g_qkvs[(size_t)sj[p + 3] * QKVS + 256 + f];
            a0 += v0 * sa[p + 0];
            a1 += v1 * sa[p + 1];
            a2 += v2 * sa[p + 2];
            a3 += v3 * sa[p + 3];
        }
        for (; p < cnt; p++)
            a0 += g_qkvs[(size_t)sj[p] * QKVS + 256 + f] * sa[p];
        __syncthreads();
    }
    out[(size_t)i * D_OUT + f] = (a0 + a1) + (a2 + a3);
}

// ---------------- launch ----------------
extern "C" void kernel_launch(void* const* d_in, const int* in_sizes, int n_in,
                              void* d_out, int out_size) {
    (void)in_sizes; (void)n_in; (void)out_size;
    const float* x     = (const float*)d_in[0];
    const int*   ei    = (const int*)d_in[1];
    const float* W_gcn = (const float*)d_in[2];
    const float* b_gcn = (const float*)d_in[3];
    const float* Wq = (const float*)d_in[4],  *bq = (const float*)d_in[5];
    const float* Wk = (const float*)d_in[6],  *bk = (const float*)d_in[7];
    const float* Wv = (const float*)d_in[8],  *bv = (const float*)d_in[9];
    const float* Ws = (const float*)d_in[10], *bs = (const float*)d_in[11];
    float* out = (float*)d_out;

    k_init<<<(N_NODES + 255) / 256, 256>>>();
    k_hist<<<(E_EDGES + 255) / 256, 256>>>(ei);
    k_scan<<<1, 1024>>>();
    k_csr<<<(E_EDGES + 255) / 256, 256>>>(ei);

    k_convA<<<(int)(((size_t)N_NODES * F_IN / 4 + 255) / 256), 256>>>(x);
    k_convBW<<<(H_MID * F_IN + 255) / 256, 256>>>(W_gcn);
    k_packB2<<<(QKVS * H_MID + 255) / 256, 256>>>(Wq, Wk, Wv, Ws, bq, bk, bv, bs);

    // g = (x @ W_gcn) * dinv[row]
    k_mmagemm<0><<<dim3(M_TILES, 2), 256>>>();

    k_agg<<<N_NODES, 128>>>(b_gcn);

    // qkvs = h @ Wcat + bcat
    k_mmagemm<1><<<dim3(M_TILES, 4), 256>>>();

    k_alpha<<<(E_EDGES + 7) / 8, 256>>>(ei);
    k_stats<<<STAT_BLOCKS, 256>>>();
    k_finalize<<<1, STAT_BLOCKS>>>();
    k_out<<<N_NODES, D_OUT>>>(out);
}

// round 11
// speedup vs baseline: 1.1756x; 1.0340x over previous
#include <cuda_runtime.h>
#include <cuda_bf16.h>
#include <math.h>
#include <stdint.h>

#define N_NODES 20000
#define E_EDGES 320000
#define F_IN    1024
#define H_MID   256
#define D_OUT   128
#define QKVS    512
#define STAT_BLOCKS 256
#define M_TILES ((N_NODES + 127) / 128)

// ---------------- scratch (static device globals; no allocations) ----------------
__device__ __align__(16) float  g_g[(size_t)N_NODES * H_MID];
__device__ __align__(16) float  g_qkvs[(size_t)N_NODES * QKVS];
__device__ __align__(16) float  g_alpha[E_EDGES];
__device__ float  g_dinv[N_NODES];
__device__ int    g_degcnt[N_NODES];
__device__ int    g_fill[N_NODES];
__device__ int    g_rowptr[N_NODES + 1];
__device__ int    g_csrc[E_EDGES];
__device__ int    g_ceid[E_EDGES];
__device__ double g_part[STAT_BLOCKS][2];
__device__ float  g_stats[2];
__device__ __align__(16) float  g_bcat[QKVS];
// bf16 split operands
__device__ __align__(16) __nv_bfloat16 g_B1hi[(size_t)H_MID * F_IN];   // W_gcn^T [256][1024]
__device__ __align__(16) __nv_bfloat16 g_B1lo[(size_t)H_MID * F_IN];
__device__ __align__(16) __nv_bfloat16 g_Hhi[(size_t)N_NODES * H_MID]; // split h
__device__ __align__(16) __nv_bfloat16 g_Hlo[(size_t)N_NODES * H_MID];
__device__ __align__(16) __nv_bfloat16 g_B2hi[(size_t)QKVS * H_MID];   // Wcat^T [512][256]
__device__ __align__(16) __nv_bfloat16 g_B2lo[(size_t)QKVS * H_MID];

// ---------------- helpers ----------------
__device__ __forceinline__ uint32_t smem_u32(const void* p) {
    uint32_t a;
    asm("{ .reg .u64 t; cvta.to.shared.u64 t, %1; cvt.u32.u64 %0, t; }" : "=r"(a) : "l"(p));
    return a;
}
__device__ __forceinline__ void mma16816(float* c, const uint32_t* a, const uint32_t* b) {
    asm volatile(
        "mma.sync.aligned.m16n8k16.row.col.f32.bf16.bf16.f32 "
        "{%0,%1,%2,%3}, {%4,%5,%6,%7}, {%8,%9}, {%0,%1,%2,%3};"
        : "+f"(c[0]), "+f"(c[1]), "+f"(c[2]), "+f"(c[3])
        : "r"(a[0]), "r"(a[1]), "r"(a[2]), "r"(a[3]), "r"(b[0]), "r"(b[1]));
}
__device__ __forceinline__ void ldm4(uint32_t* r, uint32_t addr) {
    asm volatile("ldmatrix.sync.aligned.m8n8.x4.shared.b16 {%0,%1,%2,%3}, [%4];"
        : "=r"(r[0]), "=r"(r[1]), "=r"(r[2]), "=r"(r[3]) : "r"(addr) : "memory");
}
__device__ __forceinline__ void split2(float a, float b, __nv_bfloat162& h, __nv_bfloat162& l) {
    __nv_bfloat16 ha = __float2bfloat16_rn(a);
    __nv_bfloat16 hb = __float2bfloat16_rn(b);
    h.x = ha; h.y = hb;
    l.x = __float2bfloat16_rn(a - __bfloat162float(ha));
    l.y = __float2bfloat16_rn(b - __bfloat162float(hb));
}
__device__ __forceinline__ void splitpack(float a, float b, uint32_t& hw, uint32_t& lw) {
    __nv_bfloat162 h, l;
    split2(a, b, h, l);
    hw = *(uint32_t*)&h;
    lw = *(uint32_t*)&l;
}

// ---------------- CSR build ----------------
__global__ void k_init() {
    int i = blockIdx.x * blockDim.x + threadIdx.x;
    if (i < N_NODES) { g_degcnt[i] = 0; g_fill[i] = 0; }
}

__global__ void k_hist(const int* __restrict__ ei) {
    int e = blockIdx.x * blockDim.x + threadIdx.x;
    if (e < E_EDGES) atomicAdd(&g_degcnt[ei[E_EDGES + e]], 1);
}

__global__ void k_scan() {
    const int n = N_NODES;
    const int PER = 20;
    __shared__ int wsum[32];
    int tid = threadIdx.x, lane = tid & 31, wid = tid >> 5;
    int start = tid * PER;
    int cnt[PER];
    int local = 0;
#pragma unroll
    for (int u = 0; u < PER; u++) {
        int i = start + u;
        int c = (i < n) ? g_degcnt[i] : 0;
        cnt[u] = c; local += c;
    }
    int v = local;
#pragma unroll
    for (int d = 1; d < 32; d <<= 1) { int t = __shfl_up_sync(0xffffffffu, v, d); if (lane >= d) v += t; }
    if (lane == 31) wsum[wid] = v;
    __syncthreads();
    if (wid == 0) {
        int w = wsum[lane];
#pragma unroll
        for (int d = 1; d < 32; d <<= 1) { int t = __shfl_up_sync(0xffffffffu, w, d); if (lane >= d) w += t; }
        wsum[lane] = w;
    }
    __syncthreads();
    int excl = (v - local) + (wid > 0 ? wsum[wid - 1] : 0);
    int run = excl;
#pragma unroll
    for (int u = 0; u < PER; u++) {
        int i = start + u;
        if (i < n) {
            g_rowptr[i] = run;
            g_dinv[i] = rsqrtf((float)(cnt[u] + 1));
        }
        run += cnt[u];
    }
    if (tid == 1023) g_rowptr[n] = run;
}

__global__ void k_csr(const int* __restrict__ ei) {
    int e = blockIdx.x * blockDim.x + threadIdx.x;
    if (e < E_EDGES) {
        int s = ei[e];
        int d = ei[E_EDGES + e];
        int pos = g_rowptr[d] + atomicAdd(&g_fill[d], 1);
        g_csrc[pos] = s;
        g_ceid[pos] = e;
    }
}

// ---------------- weight conversions ----------------
// W_gcn[1024,256] -> B1 [256][1024]
__global__ void k_convBW(const float* __restrict__ Wg) {
    int idx = blockIdx.x * blockDim.x + threadIdx.x;
    if (idx >= H_MID * F_IN) return;
    int n = idx >> 10, k = idx & 1023;
    float v = Wg[(size_t)k * H_MID + n];
    __nv_bfloat16 h = __float2bfloat16_rn(v);
    g_B1hi[idx] = h;
    g_B1lo[idx] = __float2bfloat16_rn(v - __bfloat162float(h));
}

// Wq|Wk|Wv|Ws [256,128] -> B2 [512][256] + bcat
__global__ void k_packB2(const float* __restrict__ Wq, const float* __restrict__ Wk,
                         const float* __restrict__ Wv, const float* __restrict__ Ws,
                         const float* __restrict__ bq, const float* __restrict__ bk,
                         const float* __restrict__ bv, const float* __restrict__ bs) {
    int idx = blockIdx.x * blockDim.x + threadIdx.x;
    if (idx >= QKVS * H_MID) return;
    int n = idx >> 8, k = idx & 255;
    int w = n >> 7, c = n & 127;
    const float* W = (w == 0) ? Wq : (w == 1) ? Wk : (w == 2) ? Wv : Ws;
    float v = W[(size_t)k * D_OUT + c];
    __nv_bfloat16 h = __float2bfloat16_rn(v);
    g_B2hi[idx] = h;
    g_B2lo[idx] = __float2bfloat16_rn(v - __bfloat162float(h));
    if (idx < QKVS) {
        int nn = idx, ww = nn >> 7, cc = nn & 127;
        const float* b = (ww == 0) ? bq : (ww == 1) ? bk : (ww == 2) ? bv : bs;
        g_bcat[nn] = b[cc];
    }
}

// ---------------- split-bf16 GEMM via mma.sync (R7/R10 pipelining order) ----------------
// MODE 0: g_g = (x @ W_gcn) * dinv[row]; A = fp32 x read directly, split in store phase
// MODE 1: g_qkvs = h @ Wcat + bcat; A = g_Hhi/Hlo
#define SPAD 24

template <int MODE>
__global__ __launch_bounds__(256)
void k_mmagemm(const float* __restrict__ X) {
    const int K_TOT = (MODE == 0) ? F_IN : H_MID;
    const __nv_bfloat16* Bhi = (MODE == 0) ? g_B1hi : g_B2hi;
    const __nv_bfloat16* Blo = (MODE == 0) ? g_B1lo : g_B2lo;

    __shared__ __align__(16) __nv_bfloat16 sAh[128 * SPAD], sAl[128 * SPAD];
    __shared__ __align__(16) __nv_bfloat16 sBh[128 * SPAD], sBl[128 * SPAD];

    int tid = threadIdx.x, wid = tid >> 5, lane = tid & 31;
    int m0 = blockIdx.x * 128, n0 = blockIdx.y * 128;
    int wm = wid & 3, wn = wid >> 2;

    int lrow = tid >> 1, lhalf = (tid & 1) << 3;
    const int NCH = K_TOT / 16;
    int arow = m0 + lrow;
    bool aok = arow < N_NODES;
    const float* pX = X + (size_t)arow * K_TOT + lhalf;               // MODE 0
    const __nv_bfloat16* pAh = g_Hhi + (size_t)arow * K_TOT + lhalf;  // MODE 1
    const __nv_bfloat16* pAl = g_Hlo + (size_t)arow * K_TOT + lhalf;
    const __nv_bfloat16* pBh = Bhi + (size_t)(n0 + lrow) * K_TOT + lhalf;
    const __nv_bfloat16* pBl = Blo + (size_t)(n0 + lrow) * K_TOT + lhalf;

    // chunk-0 preload into registers
    uint4 z4 = make_uint4(0, 0, 0, 0);
    float4 z4f = make_float4(0.f, 0.f, 0.f, 0.f);
    float4 xa = z4f, xb = z4f;        // MODE 0 fp32 A data
    uint4 vah = z4, val_ = z4;        // MODE 1 bf16 A data
    if (MODE == 0) {
        if (aok) { xa = *(const float4*)pX; xb = *(const float4*)(pX + 4); }
    } else {
        if (aok) { vah = *(const uint4*)pAh; val_ = *(const uint4*)pAl; }
    }
    uint4 vbh = *(const uint4*)pBh;
    uint4 vbl = *(const uint4*)pBl;

    float acc[2][8][4];
#pragma unroll
    for (int a = 0; a < 2; a++)
#pragma unroll
        for (int b = 0; b < 8; b++)
#pragma unroll
            for (int c = 0; c < 4; c++) acc[a][b][c] = 0.f;

    uint32_t baseAh = smem_u32(sAh), baseAl = smem_u32(sAl);
    uint32_t baseBh = smem_u32(sBh), baseBl = smem_u32(sBl);
    int soff = lrow * SPAD + lhalf;

    int g8 = lane >> 3, w8 = lane & 7;
    uint32_t a_off = (uint32_t)((((((g8 & 1) << 3) + w8) + wm * 32) * SPAD + ((g8 >> 1) << 3)) * 2);
    uint32_t b_off = (uint32_t)((((((g8 >> 1) << 3) + w8) + wn * 64) * SPAD + ((g8 & 1) << 3)) * 2);

    for (int c = 0; c < NCH; c++) {
        // ---- store phase (register data loaded one chunk ago) ----
        if (MODE == 0) {
            uint4 hw, lw;
            splitpack(xa.x, xa.y, hw.x, lw.x);
            splitpack(xa.z, xa.w, hw.y, lw.y);
            splitpack(xb.x, xb.y, hw.z, lw.z);
            splitpack(xb.z, xb.w, hw.w, lw.w);
            *(uint4*)&sAh[soff] = hw;
            *(uint4*)&sAl[soff] = lw;
        } else {
            *(uint4*)&sAh[soff] = vah;
            *(uint4*)&sAl[soff] = val_;
        }
        *(uint4*)&sBh[soff] = vbh;
        *(uint4*)&sBl[soff] = vbl;
        __syncthreads();
        // ---- issue next-chunk loads (latency hidden by ldmatrix+mma below) ----
        if (c + 1 < NCH) {
            int k0 = (c + 1) * 16;
            if (MODE == 0) {
                if (aok) { xa = *(const float4*)(pX + k0); xb = *(const float4*)(pX + k0 + 4); }
            } else {
                if (aok) { vah = *(const uint4*)(pAh + k0); val_ = *(const uint4*)(pAl + k0); }
            }
            vbh = *(const uint4*)(pBh + k0);
            vbl = *(const uint4*)(pBl + k0);
        }
        uint32_t ah[2][4], al[2][4], bh[4][4], bl[4][4];
#pragma unroll
        for (int mb = 0; mb < 2; mb++) {
            ldm4(ah[mb], baseAh + a_off + mb * 16 * SPAD * 2);
            ldm4(al[mb], baseAl + a_off + mb * 16 * SPAD * 2);
        }
#pragma unroll
        for (int q = 0; q < 4; q++) {
            ldm4(bh[q], baseBh + b_off + q * 16 * SPAD * 2);
            ldm4(bl[q], baseBl + b_off + q * 16 * SPAD * 2);
        }
#pragma unroll
        for (int mb = 0; mb < 2; mb++)
#pragma unroll
            for (int q = 0; q < 4; q++)
#pragma unroll
                for (int hh = 0; hh < 2; hh++) {
                    float* ca = acc[mb][q * 2 + hh];
                    mma16816(ca, ah[mb], &bh[q][hh * 2]);
                    mma16816(ca, al[mb], &bh[q][hh * 2]);
                    mma16816(ca, ah[mb], &bl[q][hh * 2]);
                }
        __syncthreads();
    }

    const int CS = (MODE == 0) ? H_MID : QKVS;
    float* Cp = (MODE == 0) ? g_g : g_qkvs;
#pragma unroll
    for (int mb = 0; mb < 2; mb++) {
        int rbase = m0 + wm * 32 + mb * 16 + (lane >> 2);
#pragma unroll
        for (int hf = 0; hf < 2; hf++) {
            int r = rbase + hf * 8;
            if (r >= N_NODES) continue;
            float rs = (MODE == 0) ? g_dinv[r] : 1.f;
#pragma unroll
            for (int n8 = 0; n8 < 8; n8++) {
                int col = n0 + wn * 64 + n8 * 8 + ((lane & 3) << 1);
                float v0 = acc[mb][n8][hf * 2 + 0];
                float v1 = acc[mb][n8][hf * 2 + 1];
                if (MODE == 0) { v0 *= rs; v1 *= rs; }
                else { v0 += g_bcat[col]; v1 += g_bcat[col + 1]; }
                float2 o; o.x = v0; o.y = v1;
                *(float2*)(Cp + (size_t)r * CS + col) = o;
            }
        }
    }
}

// ---------------- GCN aggregation: float2/thread, 8-way MLP unroll, split write ----------------
__global__ __launch_bounds__(128)
void k_agg(const float* __restrict__ b_gcn) {
    int i = blockIdx.x;
    int f = threadIdx.x;
    const float2* G = (const float2*)g_g;
    float2 a0 = G[(size_t)i * 128 + f];        // self loop
    float2 a1 = make_float2(0.f, 0.f), a2 = a1, a3 = a1;
    float2 a4 = a1, a5 = a1, a6 = a1, a7 = a1;
    __shared__ int sj[128];
    int s0 = g_rowptr[i], e0 = g_rowptr[i + 1];
    for (int base = s0; base < e0; base += 128) {
        int cnt = min(128, e0 - base);
        if (f < cnt) sj[f] = g_csrc[base + f];
        __syncthreads();
        int p = 0;
        for (; p + 8 <= cnt; p += 8) {
            float2 v0 = G[(size_t)sj[p + 0] * 128 + f];
            float2 v1 = G[(size_t)sj[p + 1] * 128 + f];
            float2 v2 = G[(size_t)sj[p + 2] * 128 + f];
            float2 v3 = G[(size_t)sj[p + 3] * 128 + f];
            float2 v4 = G[(size_t)sj[p + 4] * 128 + f];
            float2 v5 = G[(size_t)sj[p + 5] * 128 + f];
            float2 v6 = G[(size_t)sj[p + 6] * 128 + f];
            float2 v7 = G[(size_t)sj[p + 7] * 128 + f];
            a0.x += v0.x; a0.y += v0.y;
            a1.x += v1.x; a1.y += v1.y;
            a2.x += v2.x; a2.y += v2.y;
            a3.x += v3.x; a3.y += v3.y;
            a4.x += v4.x; a4.y += v4.y;
            a5.x += v5.x; a5.y += v5.y;
            a6.x += v6.x; a6.y += v6.y;
            a7.x += v7.x; a7.y += v7.y;
        }
        for (; p + 4 <= cnt; p += 4) {
            float2 v0 = G[(size_t)sj[p + 0] * 128 + f];
            float2 v1 = G[(size_t)sj[p + 1] * 128 + f];
            float2 v2 = G[(size_t)sj[p + 2] * 128 + f];
            float2 v3 = G[(size_t)sj[p + 3] * 128 + f];
            a0.x += v0.x; a0.y += v0.y;
            a1.x += v1.x; a1.y += v1.y;
            a2.x += v2.x; a2.y += v2.y;
            a3.x += v3.x; a3.y += v3.y;
        }
        for (; p < cnt; p++) {
            float2 v = G[(size_t)sj[p] * 128 + f];
            a0.x += v.x; a0.y += v.y;
        }
        __syncthreads();
    }
    float di = g_dinv[i];
    float2 bb = ((const float2*)b_gcn)[f];
    float vx = di * (((a0.x + a1.x) + (a2.x + a3.x)) + ((a4.x + a5.x) + (a6.x + a7.x))) + bb.x;
    float vy = di * (((a0.y + a1.y) + (a2.y + a3.y)) + ((a4.y + a5.y) + (a6.y + a7.y))) + bb.y;
    vx = (vx >= 0.f) ? vx : 0.01f * vx;
    vy = (vy >= 0.f) ? vy : 0.01f * vy;
    __nv_bfloat162 h, l;
    split2(vx, vy, h, l);
    ((__nv_bfloat162*)g_Hhi)[(size_t)i * 128 + f] = h;
    ((__nv_bfloat162*)g_Hlo)[(size_t)i * 128 + f] = l;
}

// ---------------- attention logits (R7-proven: warp per edge) ----------------
__global__ __launch_bounds__(256)
void k_alpha(const int* __restrict__ ei) {
    int warp = threadIdx.x >> 5, lane = threadIdx.x & 31;
    int e = blockIdx.x * 8 + warp;
    if (e >= E_EDGES) return;
    int s = ei[e], d = ei[E_EDGES + e];
    const float4* q = (const float4*)(g_qkvs + (size_t)d * QKVS);
    const float4* k = (const float4*)(g_qkvs + (size_t)s * QKVS + D_OUT);
    float4 a = q[lane], b = k[lane];
    float p = a.x * b.x + a.y * b.y + a.z * b.z + a.w * b.w;
#pragma unroll
    for (int o = 16; o; o >>= 1) p += __shfl_xor_sync(0xffffffffu, p, o);
    if (lane == 0) g_alpha[e] = p * 0.08838834764831845f;
}

__global__ __launch_bounds__(256)
void k_stats() {
    double s = 0.0, s2 = 0.0;
    for (int i = blockIdx.x * blockDim.x + threadIdx.x; i < E_EDGES; i += STAT_BLOCKS * 256) {
        double a = (double)g_alpha[i];
        s += a; s2 += a * a;
    }
#pragma unroll
    for (int o = 16; o; o >>= 1) {
        s  += __shfl_down_sync(0xffffffffu, s,  o);
        s2 += __shfl_down_sync(0xffffffffu, s2, o);
    }
    __shared__ double ws[8], ws2[8];
    int lane = threadIdx.x & 31, wid = threadIdx.x >> 5;
    if (lane == 0) { ws[wid] = s; ws2[wid] = s2; }
    __syncthreads();
    if (threadIdx.x == 0) {
        double ts = 0.0, ts2 = 0.0;
        for (int w = 0; w < 8; w++) { ts += ws[w]; ts2 += ws2[w]; }
        g_part[blockIdx.x][0] = ts;
        g_part[blockIdx.x][1] = ts2;
    }
}

__global__ __launch_bounds__(STAT_BLOCKS)
void k_finalize() {
    int t = threadIdx.x;
    double s = g_part[t][0], s2 = g_part[t][1];
#pragma unroll
    for (int o = 16; o; o >>= 1) {
        s  += __shfl_down_sync(0xffffffffu, s,  o);
        s2 += __shfl_down_sync(0xffffffffu, s2, o);
    }
    __shared__ double ws[8], ws2[8];
    int lane = t & 31, wid = t >> 5;
    if (lane == 0) { ws[wid] = s; ws2[wid] = s2; }
    __syncthreads();
    if (t == 0) {
        double ts = 0.0, ts2 = 0.0;
        for (int w = 0; w < STAT_BLOCKS / 32; w++) { ts += ws[w]; ts2 += ws2[w]; }
        double En = (double)E_EDGES;
        double mean = ts / En;
        double var = (ts2 - En * mean * mean) / (En - 1.0);   // ddof=1
        g_stats[0] = (float)mean;
        g_stats[1] = (float)(3.0 / sqrt(var));                // SCALE_PARAM/std
    }
}

// ---------------- output: 8-way MLP unroll ----------------
__global__ __launch_bounds__(D_OUT)
void k_out(float* __restrict__ out) {
    int i = blockIdx.x;
    int f = threadIdx.x;
    float mean = g_stats[0], sc = g_stats[1];
    float a0 = g_qkvs[(size_t)i * QKVS + 384 + f];   // skip s = h@Ws + bs
    float a1 = 0.f, a2 = 0.f, a3 = 0.f, a4 = 0.f, a5 = 0.f, a6 = 0.f, a7 = 0.f;
    __shared__ int   sj[D_OUT];
    __shared__ float sa[D_OUT];
    int s0 = g_rowptr[i], e0 = g_rowptr[i + 1];
    for (int base = s0; base < e0; base += D_OUT) {
        int cnt = min(D_OUT, e0 - base);
        if (f < cnt) {
            sj[f] = g_csrc[base + f];
            float a = (g_alpha[g_ceid[base + f]] - mean) * sc;
            sa[f] = 1.0f / (1.0f + expf(-a));
        }
        __syncthreads();
        int p = 0;
        for (; p + 8 <= cnt; p += 8) {
            float v0 = g_qkvs[(size_t)sj[p + 0] * QKVS + 256 + f];
            float v1 = g_qkvs[(size_t)sj[p + 1] * QKVS + 256 + f];
            float v2 = g_qkvs[(size_t)sj[p + 2] * QKVS + 256 + f];
            float v3 = g_qkvs[(size_t)sj[p + 3] * QKVS + 256 + f];
            float v4 = g_qkvs[(size_t)sj[p + 4] * QKVS + 256 + f];
            float v5 = g_qkvs[(size_t)sj[p + 5] * QKVS + 256 + f];
            float v6 = g_qkvs[(size_t)sj[p + 6] * QKVS + 256 + f];
            float v7 = g_qkvs[(size_t)sj[p + 7] * QKVS + 256 + f];
            a0 += v0 * sa[p + 0];
            a1 += v1 * sa[p + 1];
            a2 += v2 * sa[p + 2];
            a3 += v3 * sa[p + 3];
            a4 += v4 * sa[p + 4];
            a5 += v5 * sa[p + 5];
            a6 += v6 * sa[p + 6];
            a7 += v7 * sa[p + 7];
        }
        for (; p + 4 <= cnt; p += 4) {
            float v0 = g_qkvs[(size_t)sj[p + 0] * QKVS + 256 + f];
            float v1 = g_qkvs[(size_t)sj[p + 1] * QKVS + 256 + f];
            float v2 = g_qkvs[(size_t)sj[p + 2] * QKVS + 256 + f];
            float v3 = g_qkvs[(size_t)sj[p + 3] * QKVS + 256 + f];
            a0 += v0 * sa[p + 0];
            a1 += v1 * sa[p + 1];
            a2 += v2 * sa[p + 2];
            a3 += v3 * sa[p + 3];
        }
        for (; p < cnt; p++)
            a0 += g_qkvs[(size_t)sj[p] * QKVS + 256 + f] * sa[p];
        __syncthreads();
    }
    out[(size_t)i * D_OUT + f] = ((a0 + a1) + (a2 + a3)) + ((a4 + a5) + (a6 + a7));
}

// ---------------- launch ----------------
extern "C" void kernel_launch(void* const* d_in, const int* in_sizes, int n_in,
                              void* d_out, int out_size) {
    (void)in_sizes; (void)n_in; (void)out_size;
    const float* x     = (const float*)d_in[0];
    const int*   ei    = (const int*)d_in[1];
    const float* W_gcn = (const float*)d_in[2];
    const float* b_gcn = (const float*)d_in[3];
    const float* Wq = (const float*)d_in[4],  *bq = (const float*)d_in[5];
    const float* Wk = (const float*)d_in[6],  *bk = (const float*)d_in[7];
    const float* Wv = (const float*)d_in[8],  *bv = (const float*)d_in[9];
    const float* Ws = (const float*)d_in[10], *bs = (const float*)d_in[11];
    float* out = (float*)d_out;

    k_init<<<(N_NODES + 255) / 256, 256>>>();
    k_hist<<<(E_EDGES + 255) / 256, 256>>>(ei);
    k_scan<<<1, 1024>>>();
    k_csr<<<(E_EDGES + 255) / 256, 256>>>(ei);

    k_convBW<<<(H_MID * F_IN + 255) / 256, 256>>>(W_gcn);
    k_packB2<<<(QKVS * H_MID + 255) / 256, 256>>>(Wq, Wk, Wv, Ws, bq, bk, bv, bs);

    // g = (x @ W_gcn) * dinv[row]  (fp32 x split in-kernel, R7 pipelining order)
    k_mmagemm<0><<<dim3(M_TILES, 2), 256>>>(x);

    k_agg<<<N_NODES, 128>>>(b_gcn);

    // qkvs = h @ Wcat + bcat
    k_mmagemm<1><<<dim3(M_TILES, 4), 256>>>(nullptr);

    k_alpha<<<(E_EDGES + 7) / 8, 256>>>(ei);
    k_stats<<<STAT_BLOCKS, 256>>>();
    k_finalize<<<1, STAT_BLOCKS>>>();
    k_out<<<N_NODES, D_OUT>>>(out);
}